// round 5
// baseline (speedup 1.0000x reference)
#include <cuda_runtime.h>
#include <cuda_fp16.h>
#include <cstdint>

#define B_ROWS   8192
#define F_DIM    512
#define N_INT    1023
#define N_PAD    1024
#define N_LEAVES 1024
#define LEAF_D   64
#define DEPTH    10

// Scratch (allocation-free device global)
__device__ float g_P[B_ROWS * N_PAD];   // sigmoid(xW+b), col 1023 junk

// m16n8k16 fp16 MMA, f32 accum (sm_80+ PTX — compiles for plain compute_103)
__device__ __forceinline__ void mma_f16(float* d, const uint32_t* a,
                                        uint32_t b0, uint32_t b1) {
    asm volatile(
        "mma.sync.aligned.m16n8k16.row.col.f32.f16.f16.f32 "
        "{%0,%1,%2,%3}, {%4,%5,%6,%7}, {%8,%9}, {%0,%1,%2,%3};"
        : "+f"(d[0]), "+f"(d[1]), "+f"(d[2]), "+f"(d[3])
        : "r"(a[0]), "r"(a[1]), "r"(a[2]), "r"(a[3]), "r"(b0), "r"(b1));
}

__device__ __forceinline__ uint32_t pack_h2(__half lo, __half hi) {
    __half2 h2 = __halves2half2(lo, hi);
    return *reinterpret_cast<uint32_t*>(&h2);
}

// ===========================================================================
// Kernel 1: P = sigmoid(x @ W + b), fp16 MMA with x = x_hi + x_lo exact split
// (W quantized to fp16 once; error std ~2.8e-4 < tf32 baseline).
// BM=128, BN=128, BK=16. 256 threads = 8 warps (2M x 4N), warp tile 64x32.
// A smem: uint2 (hi_half2, lo_half2) fragment-major, pad 9. B smem: [n][k]
// halves, pad 18. Double buffered. grid = (8, 64).
// ===========================================================================
#define AI_LD 9    // uint2 per A row (8 k-pairs + pad)
#define BH_LD 18   // halves per B n-row (16 k + pad)

__global__ __launch_bounds__(256, 2)
void gemm1_fp16_kernel(const float* __restrict__ x, const float* __restrict__ W,
                       const float* __restrict__ bias)
{
    __shared__ uint2 Ai[2][128 * AI_LD];
    __shared__ __half Bh[2][128 * BH_LD];

    const int tid  = threadIdx.x;
    const int lane = tid & 31;
    const int wid  = tid >> 5;
    const int wm   = (wid & 1) * 64;
    const int wn   = (wid >> 1) * 32;
    const int row0 = blockIdx.y * 128;
    const int col0 = blockIdx.x * 128;
    const int g    = lane >> 2;     // 0..7
    const int t    = lane & 3;      // 0..3

    float acc[4][4][4];
    #pragma unroll
    for (int mt = 0; mt < 4; ++mt)
        #pragma unroll
        for (int nt = 0; nt < 4; ++nt)
            #pragma unroll
            for (int i = 0; i < 4; ++i) acc[mt][nt][i] = 0.0f;

    // x loader: rows xm, xm+64; k-quad xk (4 k's -> 2 kk slots)
    const int xm = tid >> 2;
    const int xk = (tid & 3) * 4;
    const float* xp = x + (size_t)(row0 + xm) * F_DIM + xk;
    // W loader: k-row wk (0..15), 8 cols from wn0
    const int wk  = tid >> 4;
    const int wn0 = (tid & 15) * 8;

    float4 xa, xb;
    float  wv[8];

    // prefetch tile 0
    xa = *(const float4*)(xp);
    xb = *(const float4*)(xp + 64 * F_DIM);
    {
        const float* wrow = W + (size_t)wk * N_INT + col0 + wn0;
        #pragma unroll
        for (int j = 0; j < 8; ++j)
            wv[j] = (col0 + wn0 + j < N_INT) ? wrow[j] : 0.0f;
    }

    #define STORE_A(bufi, rowi, kk0, v0, v1)                                   \
    do {                                                                       \
        __half h0 = __float2half_rn(v0), h1 = __float2half_rn(v1);             \
        __half l0 = __float2half_rn((v0) - __half2float(h0));                  \
        __half l1 = __float2half_rn((v1) - __half2float(h1));                  \
        uint2 u;                                                               \
        u.x = pack_h2(h0, h1);                                                 \
        u.y = pack_h2(l0, l1);                                                 \
        Ai[bufi][(rowi) * AI_LD + (kk0)] = u;                                  \
    } while (0)

    int buf = 0;
    {
        STORE_A(buf, xm,      xk / 2,     xa.x, xa.y);
        STORE_A(buf, xm,      xk / 2 + 1, xa.z, xa.w);
        STORE_A(buf, xm + 64, xk / 2,     xb.x, xb.y);
        STORE_A(buf, xm + 64, xk / 2 + 1, xb.z, xb.w);
        #pragma unroll
        for (int j = 0; j < 8; ++j)
            Bh[buf][(wn0 + j) * BH_LD + wk] = __float2half_rn(wv[j]);
    }
    __syncthreads();

    for (int tile = 0; tile < 32; ++tile) {
        if (tile < 31) {
            const int bk = (tile + 1) * 16;
            xa = *(const float4*)(xp + bk);
            xb = *(const float4*)(xp + 64 * F_DIM + bk);
            const float* wrow = W + (size_t)(bk + wk) * N_INT + col0 + wn0;
            #pragma unroll
            for (int j = 0; j < 8; ++j)
                wv[j] = (col0 + wn0 + j < N_INT) ? wrow[j] : 0.0f;
        }
        // compute: one k16 step, hi+lo MMAs share B frags
        {
            uint32_t b[4][2];
            #pragma unroll
            for (int nt = 0; nt < 4; ++nt) {
                const __half* bp = &Bh[buf][(wn + nt * 8 + g) * BH_LD + 2 * t];
                b[nt][0] = *(const uint32_t*)(bp);
                b[nt][1] = *(const uint32_t*)(bp + 8);
            }
            #pragma unroll
            for (int mt = 0; mt < 4; ++mt) {
                const uint2* ap = &Ai[buf][(wm + mt * 16 + g) * AI_LD + t];
                uint2 a0 = ap[0];
                uint2 a1 = ap[8 * AI_LD];
                uint2 a2 = ap[4];
                uint2 a3 = ap[8 * AI_LD + 4];
                uint32_t ahi[4] = {a0.x, a1.x, a2.x, a3.x};
                uint32_t alo[4] = {a0.y, a1.y, a2.y, a3.y};
                #pragma unroll
                for (int nt = 0; nt < 4; ++nt) {
                    mma_f16(acc[mt][nt], ahi, b[nt][0], b[nt][1]);
                    mma_f16(acc[mt][nt], alo, b[nt][0], b[nt][1]);
                }
            }
        }
        if (tile < 31) {
            const int nbuf = buf ^ 1;
            STORE_A(nbuf, xm,      xk / 2,     xa.x, xa.y);
            STORE_A(nbuf, xm,      xk / 2 + 1, xa.z, xa.w);
            STORE_A(nbuf, xm + 64, xk / 2,     xb.x, xb.y);
            STORE_A(nbuf, xm + 64, xk / 2 + 1, xb.z, xb.w);
            #pragma unroll
            for (int j = 0; j < 8; ++j)
                Bh[nbuf][(wn0 + j) * BH_LD + wk] = __float2half_rn(wv[j]);
            __syncthreads();
            buf = nbuf;
        }
    }
    #undef STORE_A

    // Epilogue: bias + sigmoid -> g_P
    #pragma unroll
    for (int nt = 0; nt < 4; ++nt) {
        const int col = col0 + wn + nt * 8 + 2 * t;
        const float b0 = (col     < N_INT) ? bias[col]     : 0.0f;
        const float b1 = (col + 1 < N_INT) ? bias[col + 1] : 0.0f;
        #pragma unroll
        for (int mt = 0; mt < 4; ++mt) {
            const int row = row0 + wm + mt * 16 + g;
            float2 v0, v1;
            v0.x = 1.0f / (1.0f + __expf(-(acc[mt][nt][0] + b0)));
            v0.y = 1.0f / (1.0f + __expf(-(acc[mt][nt][1] + b1)));
            v1.x = 1.0f / (1.0f + __expf(-(acc[mt][nt][2] + b0)));
            v1.y = 1.0f / (1.0f + __expf(-(acc[mt][nt][3] + b1)));
            *(float2*)(g_P + (size_t)row * N_PAD + col)       = v0;
            *(float2*)(g_P + (size_t)(row + 8) * N_PAD + col) = v1;
        }
    }
}

// ===========================================================================
// Kernel 2 (fused): tree expansion + out = PROB @ leaves.
// 16 rows per CTA, 512 threads, grid = 512.
// p_s[16][1033] (odd pad -> conflict-free strided reads), prob_s[l][16].
// Phase C: warp w -> k-chunk of 64; 32 FFMA per leaves float2 load.
// Reduction scratch overlaps p_s (dead after expansion).
// ===========================================================================
#define PS_LD  1033
#define F_ROWS 16
#define FUSED_SMEM ((F_ROWS * PS_LD + N_LEAVES * F_ROWS) * 4)

__global__ __launch_bounds__(512)
void fused_tree_gemm2(const float* __restrict__ leaves, float* __restrict__ out)
{
    extern __shared__ float sm[];
    float* p_s    = sm;                     // [16][1033]
    float* prob_s = sm + F_ROWS * PS_LD;    // [1024][16]
    const int tid  = threadIdx.x;
    const int row0 = blockIdx.x * F_ROWS;

    // Phase A: load 16 p rows
    const float* src = g_P + (size_t)row0 * N_PAD;
    #pragma unroll
    for (int i = 0; i < 32; ++i) {
        int idx = tid + i * 512;           // 0..16383
        int r = idx >> 10, c = idx & 1023;
        p_s[r * PS_LD + c] = src[idx];
    }
    __syncthreads();

    // Phase B: expansion -> prob_s[l*16 + r]
    #pragma unroll
    for (int i = 0; i < 32; ++i) {
        int idx = i * 512 + tid;
        int r = idx & 15;
        int l = idx >> 4;
        const float* pr = p_s + r * PS_LD;
        float w = 1.0f;
        #pragma unroll
        for (int lvl = 0; lvl < DEPTH; ++lvl) {
            int node = (1 << lvl) - 1 + (l >> (DEPTH - lvl));
            float pv = pr[node];
            int bit  = (l >> (DEPTH - 1 - lvl)) & 1;
            w *= bit ? (1.0f - pv) : pv;
        }
        prob_s[l * 16 + r] = w;
    }
    __syncthreads();

    // Phase C: warp kc handles k in [kc*64, kc*64+64); lane -> cols 2ln,2ln+1
    const int kc = tid >> 5;
    const int ln = tid & 31;
    float2 acc[F_ROWS];
    #pragma unroll
    for (int r = 0; r < F_ROWS; ++r) { acc[r].x = 0.0f; acc[r].y = 0.0f; }

    const float* lv = leaves + (size_t)(kc * 64) * LEAF_D + 2 * ln;
    const float* pp = prob_s + kc * 64 * 16;
    #pragma unroll 4
    for (int k = 0; k < 64; ++k) {
        const float2 l2 = *(const float2*)(lv + (size_t)k * LEAF_D);
        const float* pk = pp + k * 16;
        #pragma unroll
        for (int q = 0; q < 4; ++q) {
            const float4 p4 = *(const float4*)(pk + q * 4);
            acc[q * 4 + 0].x += p4.x * l2.x; acc[q * 4 + 0].y += p4.x * l2.y;
            acc[q * 4 + 1].x += p4.y * l2.x; acc[q * 4 + 1].y += p4.y * l2.y;
            acc[q * 4 + 2].x += p4.z * l2.x; acc[q * 4 + 2].y += p4.z * l2.y;
            acc[q * 4 + 3].x += p4.w * l2.x; acc[q * 4 + 3].y += p4.w * l2.y;
        }
    }

    // Reduce 16 k-chunks; scratch overlaps p_s (64KB <= 66KB region)
    float2* scr = (float2*)p_s;
    __syncthreads();   // p_s reads (phase B) and prob_s reads done
    #pragma unroll
    for (int r = 0; r < F_ROWS; ++r)
        scr[(r * 16 + kc) * 32 + ln] = acc[r];
    __syncthreads();

    {
        const int r = tid >> 5;            // 0..15
        float2 s; s.x = 0.0f; s.y = 0.0f;
        #pragma unroll
        for (int q = 0; q < 16; ++q) {
            float2 v = scr[(r * 16 + q) * 32 + ln];
            s.x += v.x; s.y += v.y;
        }
        *(float2*)(out + (size_t)(row0 + r) * LEAF_D + 2 * ln) = s;
    }
}

// ===========================================================================
extern "C" void kernel_launch(void* const* d_in, const int* in_sizes, int n_in,
                              void* d_out, int out_size)
{
    const float* x      = (const float*)d_in[0];   // [8192, 512]
    const float* W      = (const float*)d_in[1];   // [512, 1023]
    const float* bias   = (const float*)d_in[2];   // [1023]
    const float* leaves = (const float*)d_in[3];   // [1024, 64]
    float*       out    = (float*)d_out;           // [8192, 64]

    cudaFuncSetAttribute(fused_tree_gemm2,
                         cudaFuncAttributeMaxDynamicSharedMemorySize, FUSED_SMEM);

    gemm1_fp16_kernel<<<dim3(8, 64), 256>>>(x, W, bias);
    fused_tree_gemm2<<<512, 512, FUSED_SMEM>>>(leaves, out);
}

// round 7
// speedup vs baseline: 1.1364x; 1.1364x over previous
#include <cuda_runtime.h>
#include <cuda_fp16.h>
#include <cstdint>

#define B_ROWS   8192
#define F_DIM    512
#define N_INT    1023
#define N_PAD    1024
#define N_LEAVES 1024
#define LEAF_D   64
#define DEPTH    10

// Scratch (allocation-free device global)
__device__ float g_P[B_ROWS * N_PAD];   // sigmoid(xW+b), col 1023 junk

// m16n8k16 fp16 MMA, f32 accum (sm_80+ PTX — compiles for plain compute_103)
__device__ __forceinline__ void mma_f16(float* d, const uint32_t* a,
                                        uint32_t b0, uint32_t b1) {
    asm volatile(
        "mma.sync.aligned.m16n8k16.row.col.f32.f16.f16.f32 "
        "{%0,%1,%2,%3}, {%4,%5,%6,%7}, {%8,%9}, {%0,%1,%2,%3};"
        : "+f"(d[0]), "+f"(d[1]), "+f"(d[2]), "+f"(d[3])
        : "r"(a[0]), "r"(a[1]), "r"(a[2]), "r"(a[3]), "r"(b0), "r"(b1));
}

__device__ __forceinline__ uint32_t pack_h2(__half lo, __half hi) {
    __half2 h2 = __halves2half2(lo, hi);
    return *reinterpret_cast<uint32_t*>(&h2);
}

// ===========================================================================
// Kernel 1: P = sigmoid(x @ W + b), pure fp16 MMA (both operands rn-rounded).
// BM=128, BN=128, BK=16. 256 threads = 8 warps (2M x 4N), warp tile 64x32.
// 16 HMMA per warp per k16 tile. Double-buffered smem. grid = (8, 64).
// W loads are SCALAR — W row stride is 1023 floats (4092 B), so float4
// loads are misaligned (R6 crash).
// ===========================================================================
#define AI_LD 9    // uint32 (half2) per A row (8 k-pairs + pad)
#define BH_LD 18   // halves per B n-row (16 k + pad)

__global__ __launch_bounds__(256, 2)
void gemm1_fp16_kernel(const float* __restrict__ x, const float* __restrict__ W,
                       const float* __restrict__ bias)
{
    __shared__ uint32_t Ai[2][128 * AI_LD];
    __shared__ __half  Bh[2][128 * BH_LD];

    const int tid  = threadIdx.x;
    const int lane = tid & 31;
    const int wid  = tid >> 5;
    const int wm   = (wid & 1) * 64;
    const int wn   = (wid >> 1) * 32;
    const int row0 = blockIdx.y * 128;
    const int col0 = blockIdx.x * 128;
    const int g    = lane >> 2;     // 0..7
    const int t    = lane & 3;      // 0..3

    float acc[4][4][4];
    #pragma unroll
    for (int mt = 0; mt < 4; ++mt)
        #pragma unroll
        for (int nt = 0; nt < 4; ++nt)
            #pragma unroll
            for (int i = 0; i < 4; ++i) acc[mt][nt][i] = 0.0f;

    // x loader: rows xm, xm+64; k-quad xk (4 k's -> 2 half2 slots)
    const int xm = tid >> 2;
    const int xk = (tid & 3) * 4;
    const float* xp = x + (size_t)(row0 + xm) * F_DIM + xk;
    // W loader: k-row wk (0..15), 8 cols from wn0
    const int wk  = tid >> 4;
    const int wn0 = (tid & 15) * 8;

    float4 xa, xb;
    float  wv[8];

    #define LOAD_W(bk)                                                         \
    do {                                                                       \
        const float* wrow = W + (size_t)((bk) + wk) * N_INT + col0 + wn0;      \
        _Pragma("unroll")                                                      \
        for (int j = 0; j < 8; ++j)                                            \
            wv[j] = (col0 + wn0 + j < N_INT) ? wrow[j] : 0.0f;                 \
    } while (0)

    #define STORE_A(bufi, rowi, kk0, v0, v1)                                   \
        Ai[bufi][(rowi) * AI_LD + (kk0)] =                                     \
            pack_h2(__float2half_rn(v0), __float2half_rn(v1))

    #define STORE_TILE(bufi)                                                   \
    do {                                                                       \
        STORE_A(bufi, xm,      xk / 2,     xa.x, xa.y);                        \
        STORE_A(bufi, xm,      xk / 2 + 1, xa.z, xa.w);                        \
        STORE_A(bufi, xm + 64, xk / 2,     xb.x, xb.y);                        \
        STORE_A(bufi, xm + 64, xk / 2 + 1, xb.z, xb.w);                        \
        _Pragma("unroll")                                                      \
        for (int j = 0; j < 8; ++j)                                            \
            Bh[bufi][(wn0 + j) * BH_LD + wk] = __float2half_rn(wv[j]);         \
    } while (0)

    // prefetch + store tile 0
    xa = *(const float4*)(xp);
    xb = *(const float4*)(xp + 64 * F_DIM);
    LOAD_W(0);
    int buf = 0;
    STORE_TILE(buf);
    __syncthreads();

    for (int tile = 0; tile < 32; ++tile) {
        if (tile < 31) {
            const int bk = (tile + 1) * 16;
            xa = *(const float4*)(xp + bk);
            xb = *(const float4*)(xp + 64 * F_DIM + bk);
            LOAD_W(bk);
        }
        // compute current k16 tile: 16 HMMA per warp
        {
            uint32_t b[4][2];
            #pragma unroll
            for (int nt = 0; nt < 4; ++nt) {
                const __half* bp = &Bh[buf][(wn + nt * 8 + g) * BH_LD + 2 * t];
                b[nt][0] = *(const uint32_t*)(bp);
                b[nt][1] = *(const uint32_t*)(bp + 8);
            }
            #pragma unroll
            for (int mt = 0; mt < 4; ++mt) {
                const uint32_t* ap = &Ai[buf][(wm + mt * 16 + g) * AI_LD + t];
                uint32_t a[4];
                a[0] = ap[0];
                a[1] = ap[8 * AI_LD];
                a[2] = ap[4];
                a[3] = ap[8 * AI_LD + 4];
                #pragma unroll
                for (int nt = 0; nt < 4; ++nt)
                    mma_f16(acc[mt][nt], a, b[nt][0], b[nt][1]);
            }
        }
        if (tile < 31) {
            const int nbuf = buf ^ 1;
            STORE_TILE(nbuf);
            __syncthreads();
            buf = nbuf;
        }
    }
    #undef STORE_TILE
    #undef STORE_A
    #undef LOAD_W

    // Epilogue: bias + sigmoid -> g_P
    #pragma unroll
    for (int nt = 0; nt < 4; ++nt) {
        const int col = col0 + wn + nt * 8 + 2 * t;
        const float b0 = (col     < N_INT) ? bias[col]     : 0.0f;
        const float b1 = (col + 1 < N_INT) ? bias[col + 1] : 0.0f;
        #pragma unroll
        for (int mt = 0; mt < 4; ++mt) {
            const int row = row0 + wm + mt * 16 + g;
            float2 v0, v1;
            v0.x = 1.0f / (1.0f + __expf(-(acc[mt][nt][0] + b0)));
            v0.y = 1.0f / (1.0f + __expf(-(acc[mt][nt][1] + b1)));
            v1.x = 1.0f / (1.0f + __expf(-(acc[mt][nt][2] + b0)));
            v1.y = 1.0f / (1.0f + __expf(-(acc[mt][nt][3] + b1)));
            *(float2*)(g_P + (size_t)row * N_PAD + col)       = v0;
            *(float2*)(g_P + (size_t)(row + 8) * N_PAD + col) = v1;
        }
    }
}

// ===========================================================================
// Kernel 2 (fused): tree expansion + out = PROB @ leaves.
// 8 rows per CTA, 256 threads, grid = 1024, 3 CTAs/SM (49KB smem).
// prob_s stored fp16 ([l][8] = 16B/row -> one broadcast LDS.128 per k).
// Reduction scratch overlaps p_s (dead after expansion).
// ===========================================================================
#define PS_LD  1033
#define F_ROWS 8
#define FUSED_SMEM ((F_ROWS * PS_LD) * 4 + N_LEAVES * F_ROWS * 2)

__global__ __launch_bounds__(256, 3)
void fused_tree_gemm2(const float* __restrict__ leaves, float* __restrict__ out)
{
    extern __shared__ float sm[];
    float*  p_s    = sm;                                  // [8][1033] f32
    __half* prob_s = (__half*)(sm + F_ROWS * PS_LD);      // [1024][8] f16
    const int tid  = threadIdx.x;
    const int row0 = blockIdx.x * F_ROWS;

    // Phase A: load 8 p rows
    const float* src = g_P + (size_t)row0 * N_PAD;
    #pragma unroll
    for (int i = 0; i < 32; ++i) {
        int idx = tid + i * 256;           // 0..8191
        int r = idx >> 10, c = idx & 1023;
        p_s[r * PS_LD + c] = src[idx];
    }
    __syncthreads();

    // Phase B: expansion -> prob_s[l*8 + r] (fp16)
    #pragma unroll
    for (int i = 0; i < 32; ++i) {
        int idx = i * 256 + tid;
        int r = idx & 7;
        int l = idx >> 3;
        const float* pr = p_s + r * PS_LD;
        float w = 1.0f;
        #pragma unroll
        for (int lvl = 0; lvl < DEPTH; ++lvl) {
            int node = (1 << lvl) - 1 + (l >> (DEPTH - lvl));
            float pv = pr[node];
            int bit  = (l >> (DEPTH - 1 - lvl)) & 1;
            w *= bit ? (1.0f - pv) : pv;
        }
        prob_s[l * 8 + r] = __float2half_rn(w);
    }
    __syncthreads();

    // Phase C: warp kc handles k in [kc*128, kc*128+128); lane -> 2 cols
    const int kc = tid >> 5;
    const int ln = tid & 31;
    float2 acc[F_ROWS];
    #pragma unroll
    for (int r = 0; r < F_ROWS; ++r) { acc[r].x = 0.0f; acc[r].y = 0.0f; }

    const float* lv = leaves + (size_t)(kc * 128) * LEAF_D + 2 * ln;
    const uint4* pp = (const uint4*)(prob_s + kc * 128 * 8);
    #pragma unroll 4
    for (int k = 0; k < 128; ++k) {
        const float2 l2 = *(const float2*)(lv + (size_t)k * LEAF_D);
        const uint4  u  = pp[k];               // 8 fp16 probs (broadcast)
        float2 p01 = __half22float2(*(const __half2*)&u.x);
        float2 p23 = __half22float2(*(const __half2*)&u.y);
        float2 p45 = __half22float2(*(const __half2*)&u.z);
        float2 p67 = __half22float2(*(const __half2*)&u.w);
        acc[0].x += p01.x * l2.x; acc[0].y += p01.x * l2.y;
        acc[1].x += p01.y * l2.x; acc[1].y += p01.y * l2.y;
        acc[2].x += p23.x * l2.x; acc[2].y += p23.x * l2.y;
        acc[3].x += p23.y * l2.x; acc[3].y += p23.y * l2.y;
        acc[4].x += p45.x * l2.x; acc[4].y += p45.x * l2.y;
        acc[5].x += p45.y * l2.x; acc[5].y += p45.y * l2.y;
        acc[6].x += p67.x * l2.x; acc[6].y += p67.x * l2.y;
        acc[7].x += p67.y * l2.x; acc[7].y += p67.y * l2.y;
    }

    // Reduce 8 k-chunks; scratch overlaps p_s (16KB <= 33KB region)
    float2* scr = (float2*)p_s;
    __syncthreads();   // phase B p_s reads and prob_s reads done
    #pragma unroll
    for (int r = 0; r < F_ROWS; ++r)
        scr[(r * 8 + kc) * 32 + ln] = acc[r];
    __syncthreads();

    {
        const int r = tid >> 5;            // 0..7
        float2 s; s.x = 0.0f; s.y = 0.0f;
        #pragma unroll
        for (int q = 0; q < 8; ++q) {
            float2 v = scr[(r * 8 + q) * 32 + ln];
            s.x += v.x; s.y += v.y;
        }
        *(float2*)(out + (size_t)(row0 + r) * LEAF_D + 2 * ln) = s;
    }
}

// ===========================================================================
extern "C" void kernel_launch(void* const* d_in, const int* in_sizes, int n_in,
                              void* d_out, int out_size)
{
    const float* x      = (const float*)d_in[0];   // [8192, 512]
    const float* W      = (const float*)d_in[1];   // [512, 1023]
    const float* bias   = (const float*)d_in[2];   // [1023]
    const float* leaves = (const float*)d_in[3];   // [1024, 64]
    float*       out    = (float*)d_out;           // [8192, 64]

    cudaFuncSetAttribute(fused_tree_gemm2,
                         cudaFuncAttributeMaxDynamicSharedMemorySize, FUSED_SMEM);

    gemm1_fp16_kernel<<<dim3(8, 64), 256>>>(x, W, bias);
    fused_tree_gemm2<<<1024, 256, FUSED_SMEM>>>(leaves, out);
}

// round 8
// speedup vs baseline: 2.3274x; 2.0480x over previous
#include <cuda_runtime.h>
#include <cuda_fp16.h>
#include <cstdint>

#define B_ROWS   8192
#define F_DIM    512
#define N_INT    1023
#define N_PAD    1024
#define N_LEAVES 1024
#define LEAF_D   64
#define DEPTH    10

// Scratch (allocation-free device globals)
__device__ float  g_P[B_ROWS * N_PAD];      // sigmoid(xW+b), col 1023 junk
__device__ __half g_Xh[B_ROWS * F_DIM];     // x in fp16
__device__ __half g_Wh[N_PAD * F_DIM];      // W^T in fp16: [n][k], row 1023 zero

__device__ __forceinline__ uint32_t smem_u32(const void* p) {
    uint32_t a;
    asm("{ .reg .u64 t; cvta.to.shared.u64 t, %1; cvt.u32.u64 %0, t; }" : "=r"(a) : "l"(p));
    return a;
}

// m16n8k16 fp16 MMA, f32 accum
__device__ __forceinline__ void mma_f16(float* d, const uint32_t* a,
                                        uint32_t b0, uint32_t b1) {
    asm volatile(
        "mma.sync.aligned.m16n8k16.row.col.f32.f16.f16.f32 "
        "{%0,%1,%2,%3}, {%4,%5,%6,%7}, {%8,%9}, {%0,%1,%2,%3};"
        : "+f"(d[0]), "+f"(d[1]), "+f"(d[2]), "+f"(d[3])
        : "r"(a[0]), "r"(a[1]), "r"(a[2]), "r"(a[3]), "r"(b0), "r"(b1));
}

#define LDSM_X4(r0, r1, r2, r3, addr)                                          \
    asm volatile("ldmatrix.sync.aligned.m8n8.x4.shared.b16 {%0,%1,%2,%3}, [%4];" \
                 : "=r"(r0), "=r"(r1), "=r"(r2), "=r"(r3) : "r"(addr))

#define CP_ASYNC16(saddr, gptr)                                                \
    asm volatile("cp.async.cg.shared.global [%0], [%1], 16;"                   \
                 :: "r"(saddr), "l"(gptr) : "memory")
#define CP_COMMIT()  asm volatile("cp.async.commit_group;" ::: "memory")
#define CP_WAIT1()   asm volatile("cp.async.wait_group 1;" ::: "memory")

// ===========================================================================
// Converters (run once per launch; ~5 us total)
// ===========================================================================
__global__ __launch_bounds__(256)
void convert_x_kernel(const float* __restrict__ x)
{
    const int i = (blockIdx.x * 256 + threadIdx.x) * 8;
    float4 v0 = *(const float4*)(x + i);
    float4 v1 = *(const float4*)(x + i + 4);
    __half2 h0 = __floats2half2_rn(v0.x, v0.y);
    __half2 h1 = __floats2half2_rn(v0.z, v0.w);
    __half2 h2 = __floats2half2_rn(v1.x, v1.y);
    __half2 h3 = __floats2half2_rn(v1.z, v1.w);
    uint4 u;
    u.x = *(uint32_t*)&h0; u.y = *(uint32_t*)&h1;
    u.z = *(uint32_t*)&h2; u.w = *(uint32_t*)&h3;
    *(uint4*)(g_Xh + i) = u;
}

__global__ void convert_w_kernel(const float* __restrict__ W)
{
    __shared__ float t[32][33];
    const int tx = threadIdx.x, ty = threadIdx.y;
    const int n0 = blockIdx.x * 32, k0 = blockIdx.y * 32;
    #pragma unroll
    for (int i = 0; i < 4; ++i) {
        int k = k0 + ty + i * 8;
        int n = n0 + tx;
        t[ty + i * 8][tx] = (n < N_INT) ? W[(size_t)k * N_INT + n] : 0.0f;
    }
    __syncthreads();
    #pragma unroll
    for (int i = 0; i < 4; ++i) {
        int n = n0 + ty + i * 8;
        g_Wh[(size_t)n * F_DIM + k0 + tx] = __float2half_rn(t[tx][ty + i * 8]);
    }
}

// ===========================================================================
// Kernel 1: P = sigmoid(x @ W + b). fp16 ldmatrix + mma, cp.async 3-stage.
// BM=128, BN=128, BK=32 halves. 256 threads = 8 warps (2M x 4N), warp 64x32.
// smem stage: 128 rows x 64B, XOR swizzle chunk c ^= (r>>1)&3 (16B units):
// conflict-free ldmatrix AND optimal cp.async stores. grid = (8, 64).
// ===========================================================================
#define G1_STAGE  8192
#define G1_SMEM   (6 * G1_STAGE)   // 3 stages x (A + B) = 49152

__global__ __launch_bounds__(256, 2)
void gemm1_kernel(const float* __restrict__ bias)
{
    extern __shared__ char smem[];
    const uint32_t sbase = smem_u32(smem);
    const int tid  = threadIdx.x;
    const int lane = tid & 31;
    const int wid  = tid >> 5;
    const int wm   = (wid & 1) * 64;
    const int wn   = (wid >> 1) * 32;
    const int row0 = blockIdx.y * 128;
    const int col0 = blockIdx.x * 128;

    float acc[4][4][4];
    #pragma unroll
    for (int mt = 0; mt < 4; ++mt)
        #pragma unroll
        for (int nt = 0; nt < 4; ++nt)
            #pragma unroll
            for (int i = 0; i < 4; ++i) acc[mt][nt][i] = 0.0f;

    // ---- async loader: thread covers rows lr0 and lr0+64, 16B chunk lc ----
    const int lr0 = tid >> 2;          // 0..63
    const int lc  = tid & 3;           // 16B chunk in 64B row
    const int lr1 = lr0 + 64;
    const uint32_t soff0 = (uint32_t)(lr0 * 64 + ((lc ^ ((lr0 >> 1) & 3)) << 4));
    const uint32_t soff1 = (uint32_t)(lr1 * 64 + ((lc ^ ((lr1 >> 1) & 3)) << 4));
    const __half* gA0 = g_Xh + (size_t)(row0 + lr0) * F_DIM + lc * 8;
    const __half* gA1 = g_Xh + (size_t)(row0 + lr1) * F_DIM + lc * 8;
    const __half* gB0 = g_Wh + (size_t)(col0 + lr0) * F_DIM + lc * 8;
    const __half* gB1 = g_Wh + (size_t)(col0 + lr1) * F_DIM + lc * 8;

    #define LOAD_STAGE(st, bk)                                                 \
    do {                                                                       \
        uint32_t a_ = sbase + (st) * G1_STAGE;                                 \
        uint32_t b_ = sbase + 3 * G1_STAGE + (st) * G1_STAGE;                  \
        CP_ASYNC16(a_ + soff0, gA0 + (bk));                                    \
        CP_ASYNC16(a_ + soff1, gA1 + (bk));                                    \
        CP_ASYNC16(b_ + soff0, gB0 + (bk));                                    \
        CP_ASYNC16(b_ + soff1, gB1 + (bk));                                    \
    } while (0)

    // ---- ldmatrix per-lane addresses (two k16 sections s=0,1) ----
    const int arow = wm + (lane & 15);
    const int ax   = (arow >> 1) & 3;
    const int ahi  = lane >> 4;                   // k-chunk low bit
    const uint32_t aAddr0 = (uint32_t)(arow * 64 + (((0 + ahi) ^ ax) << 4));
    const uint32_t aAddr1 = (uint32_t)(arow * 64 + (((2 + ahi) ^ ax) << 4));

    const int brow = wn + (lane & 7) + ((lane >> 4) << 3);
    const int bx   = (brow >> 1) & 3;
    const int bhi  = (lane >> 3) & 1;
    const uint32_t bAddr0 = (uint32_t)(brow * 64 + (((0 + bhi) ^ bx) << 4));
    const uint32_t bAddr1 = (uint32_t)(brow * 64 + (((2 + bhi) ^ bx) << 4));

    #define COMPUTE(st)                                                        \
    do {                                                                       \
        const uint32_t ab = sbase + (st) * G1_STAGE;                           \
        const uint32_t bb = sbase + 3 * G1_STAGE + (st) * G1_STAGE;            \
        _Pragma("unroll")                                                      \
        for (int s = 0; s < 2; ++s) {                                          \
            const uint32_t aA = (s == 0) ? aAddr0 : aAddr1;                    \
            const uint32_t bA = (s == 0) ? bAddr0 : bAddr1;                    \
            uint32_t a[4][4], b[2][4];                                         \
            _Pragma("unroll")                                                  \
            for (int mt = 0; mt < 4; ++mt)                                     \
                LDSM_X4(a[mt][0], a[mt][1], a[mt][2], a[mt][3],                \
                        ab + aA + mt * 1024);                                  \
            _Pragma("unroll")                                                  \
            for (int n2 = 0; n2 < 2; ++n2)                                     \
                LDSM_X4(b[n2][0], b[n2][1], b[n2][2], b[n2][3],                \
                        bb + bA + n2 * 1024);                                  \
            _Pragma("unroll")                                                  \
            for (int mt = 0; mt < 4; ++mt)                                     \
                _Pragma("unroll")                                              \
                for (int nt = 0; nt < 4; ++nt)                                 \
                    mma_f16(acc[mt][nt], a[mt],                                \
                            b[nt >> 1][(nt & 1) * 2],                          \
                            b[nt >> 1][(nt & 1) * 2 + 1]);                     \
        }                                                                      \
    } while (0)

    LOAD_STAGE(0, 0);  CP_COMMIT();
    LOAD_STAGE(1, 32); CP_COMMIT();

    for (int it = 0; it < 16; ++it) {
        CP_WAIT1();
        __syncthreads();
        if (it < 14) LOAD_STAGE((it + 2) % 3, (it + 2) * 32);
        CP_COMMIT();
        COMPUTE(it % 3);
    }
    #undef COMPUTE
    #undef LOAD_STAGE

    // Epilogue: bias + sigmoid -> g_P
    const int g = lane >> 2, t = lane & 3;
    #pragma unroll
    for (int nt = 0; nt < 4; ++nt) {
        const int col = col0 + wn + nt * 8 + 2 * t;
        const float b0 = (col     < N_INT) ? bias[col]     : 0.0f;
        const float b1 = (col + 1 < N_INT) ? bias[col + 1] : 0.0f;
        #pragma unroll
        for (int mt = 0; mt < 4; ++mt) {
            const int row = row0 + wm + mt * 16 + g;
            float2 v0, v1;
            v0.x = 1.0f / (1.0f + __expf(-(acc[mt][nt][0] + b0)));
            v0.y = 1.0f / (1.0f + __expf(-(acc[mt][nt][1] + b1)));
            v1.x = 1.0f / (1.0f + __expf(-(acc[mt][nt][2] + b0)));
            v1.y = 1.0f / (1.0f + __expf(-(acc[mt][nt][3] + b1)));
            *(float2*)(g_P + (size_t)row * N_PAD + col)       = v0;
            *(float2*)(g_P + (size_t)(row + 8) * N_PAD + col) = v1;
        }
    }
}

// ===========================================================================
// Kernel 2 (fused): tree expansion + out = PROB @ leaves.
// 8 rows per CTA, 256 threads, grid = 1024. prob_s f32 [l][8].
// Phase B: leaf PAIRS share 9 of 10 levels (~2x fewer ops).
// Phase C: 16 k-chunks x 16 lanes x 4 cols -> 32 FFMA per ~37 slots.
// Reduction scratch (32KB) overlaps p_s (33KB, dead after phase B).
// ===========================================================================
#define PS_LD  1033
#define F_ROWS 8
#define FUSED_SMEM ((F_ROWS * PS_LD + N_LEAVES * F_ROWS) * 4)   // 65824

__global__ __launch_bounds__(256, 3)
void fused_tree_gemm2(const float* __restrict__ leaves, float* __restrict__ out)
{
    extern __shared__ float sm[];
    float* p_s    = sm;                       // [8][1033] f32 (also scr later)
    float* prob_s = sm + F_ROWS * PS_LD;      // [1024][8] f32
    const int tid  = threadIdx.x;
    const int row0 = blockIdx.x * F_ROWS;

    // Phase A: load 8 p rows
    const float* src = g_P + (size_t)row0 * N_PAD;
    #pragma unroll
    for (int i = 0; i < 32; ++i) {
        int idx = tid + i * 256;           // 0..8191
        int r = idx >> 10, c = idx & 1023;
        p_s[r * PS_LD + c] = src[idx];
    }
    __syncthreads();

    // Phase B: leaf pairs. lp in 0..511; leaves 2lp, 2lp+1 share levels 0..8.
    #pragma unroll
    for (int i = 0; i < 16; ++i) {
        int idx = i * 256 + tid;           // 0..4095
        int r  = idx & 7;
        int lp = idx >> 3;                 // 0..511
        const float* pr = p_s + r * PS_LD;
        float w = 1.0f;
        #pragma unroll
        for (int lvl = 0; lvl < 9; ++lvl) {
            int node = (1 << lvl) - 1 + (lp >> (9 - lvl));
            float pv = pr[node];
            int bit  = (lp >> (8 - lvl)) & 1;
            w *= bit ? (1.0f - pv) : pv;
        }
        float p9 = pr[511 + lp];
        prob_s[(2 * lp)     * 8 + r] = w * p9;
        prob_s[(2 * lp + 1) * 8 + r] = w * (1.0f - p9);
    }
    __syncthreads();

    // Phase C: kc = tid>>4 handles k in [kc*64, kc*64+64); ln*4 cols.
    const int kc = tid >> 4;               // 0..15
    const int ln = tid & 15;               // 0..15
    const int c0 = ln * 4;
    float4 acc[F_ROWS];
    #pragma unroll
    for (int r = 0; r < F_ROWS; ++r) acc[r] = make_float4(0.f, 0.f, 0.f, 0.f);

    const float* lv = leaves + (size_t)(kc * 64) * LEAF_D + c0;
    const float* pp = prob_s + kc * 64 * 8;
    #pragma unroll 4
    for (int k = 0; k < 64; ++k) {
        const float4 lf = *(const float4*)(lv + (size_t)k * LEAF_D);
        const float4 pa = *(const float4*)(pp + k * 8);
        const float4 pb = *(const float4*)(pp + k * 8 + 4);
        acc[0].x += pa.x * lf.x; acc[0].y += pa.x * lf.y; acc[0].z += pa.x * lf.z; acc[0].w += pa.x * lf.w;
        acc[1].x += pa.y * lf.x; acc[1].y += pa.y * lf.y; acc[1].z += pa.y * lf.z; acc[1].w += pa.y * lf.w;
        acc[2].x += pa.z * lf.x; acc[2].y += pa.z * lf.y; acc[2].z += pa.z * lf.z; acc[2].w += pa.z * lf.w;
        acc[3].x += pa.w * lf.x; acc[3].y += pa.w * lf.y; acc[3].z += pa.w * lf.z; acc[3].w += pa.w * lf.w;
        acc[4].x += pb.x * lf.x; acc[4].y += pb.x * lf.y; acc[4].z += pb.x * lf.z; acc[4].w += pb.x * lf.w;
        acc[5].x += pb.y * lf.x; acc[5].y += pb.y * lf.y; acc[5].z += pb.y * lf.z; acc[5].w += pb.y * lf.w;
        acc[6].x += pb.z * lf.x; acc[6].y += pb.z * lf.y; acc[6].z += pb.z * lf.z; acc[6].w += pb.z * lf.w;
        acc[7].x += pb.w * lf.x; acc[7].y += pb.w * lf.y; acc[7].z += pb.w * lf.z; acc[7].w += pb.w * lf.w;
    }

    // Partials into scr (overlaps p_s; p_s dead since phase B sync)
    float* scr = p_s;                      // [8][16][64] f32 = 32KB
    #pragma unroll
    for (int r = 0; r < F_ROWS; ++r)
        *(float4*)(scr + (r * 16 + kc) * 64 + c0) = acc[r];
    __syncthreads();

    // Final reduction: thread (r = tid>>5, 2 cols)
    {
        const int r  = tid >> 5;           // 0..7
        const int c2 = (tid & 31) * 2;
        float2 s; s.x = 0.0f; s.y = 0.0f;
        #pragma unroll
        for (int q = 0; q < 16; ++q) {
            float2 v = *(const float2*)(scr + (r * 16 + q) * 64 + c2);
            s.x += v.x; s.y += v.y;
        }
        *(float2*)(out + (size_t)(row0 + r) * LEAF_D + c2) = s;
    }
}

// ===========================================================================
extern "C" void kernel_launch(void* const* d_in, const int* in_sizes, int n_in,
                              void* d_out, int out_size)
{
    const float* x      = (const float*)d_in[0];   // [8192, 512]
    const float* W      = (const float*)d_in[1];   // [512, 1023]
    const float* bias   = (const float*)d_in[2];   // [1023]
    const float* leaves = (const float*)d_in[3];   // [1024, 64]
    float*       out    = (float*)d_out;           // [8192, 64]

    cudaFuncSetAttribute(gemm1_kernel,
                         cudaFuncAttributeMaxDynamicSharedMemorySize, G1_SMEM);
    cudaFuncSetAttribute(fused_tree_gemm2,
                         cudaFuncAttributeMaxDynamicSharedMemorySize, FUSED_SMEM);

    convert_x_kernel<<<B_ROWS * F_DIM / (256 * 8), 256>>>(x);
    convert_w_kernel<<<dim3(32, 16), dim3(32, 8)>>>(W);
    gemm1_kernel<<<dim3(8, 64), 256, G1_SMEM>>>(bias);
    fused_tree_gemm2<<<1024, 256, FUSED_SMEM>>>(leaves, out);
}